// round 6
// baseline (speedup 1.0000x reference)
#include <cuda_runtime.h>
#include <cstdint>
#include <cuda_bf16.h>

#define B_ 8
#define E_ 512
#define L_ 8192
#define KS_ 5
#define LC_ (L_ - KS_ + 1)   // 8188
#define NB3_ 2730
#define KT_ (E_ * KS_)       // 2560

// conv GEMM tiling
#define BKc 32               // e_in per chunk
#define NCH 80               // 16 e_in-chunks x 5 taps
#define ROWB 80              // padded smem row stride (bytes), 64B payload
#define TILE_B (128 * ROWB)  // 10240 per operand tile
#define STAGE_B (4 * TILE_B) // Ah, Al, Bh, Bl
#define CSMEM (3 * STAGE_B)  // 122880, 3-stage pipeline

__device__ float g_y[(size_t)B_ * E_ * L_];
__device__ float g_s[(size_t)B_ * L_];
__device__ __align__(16) __nv_bfloat16 g_xth[(size_t)B_ * L_ * E_]; // [b][t][e] hi
__device__ __align__(16) __nv_bfloat16 g_xtl[(size_t)B_ * L_ * E_]; // [b][t][e] lo
__device__ __align__(16) __nv_bfloat16 g_wh[(size_t)E_ * KT_];      // [eo][tap][ein]
__device__ __align__(16) __nv_bfloat16 g_wl[(size_t)E_ * KT_];

__device__ __forceinline__ uint32_t smem_u32(const void* p) {
    uint32_t a;
    asm("{ .reg .u64 t; cvta.to.shared.u64 t, %1; cvt.u32.u64 %0, t; }" : "=r"(a) : "l"(p));
    return a;
}
#define CP16(dst, src) \
    asm volatile("cp.async.cg.shared.global [%0], [%1], 16;" :: "r"(dst), "l"(src) : "memory")
#define CP_COMMIT() asm volatile("cp.async.commit_group;" ::: "memory")
#define CP_WAIT1() asm volatile("cp.async.wait_group 1;" ::: "memory")

#define LDSM4(r, a) \
    asm volatile("ldmatrix.sync.aligned.m8n8.x4.shared.b16 {%0,%1,%2,%3}, [%4];" \
        : "=r"((r)[0]), "=r"((r)[1]), "=r"((r)[2]), "=r"((r)[3]) : "r"(a))

#define MMA(c, A, b0, b1) \
    asm volatile("mma.sync.aligned.m16n8k16.row.col.f32.bf16.bf16.f32 " \
        "{%0,%1,%2,%3},{%4,%5,%6,%7},{%8,%9},{%0,%1,%2,%3};" \
        : "+f"((c)[0]), "+f"((c)[1]), "+f"((c)[2]), "+f"((c)[3]) \
        : "r"((A)[0]), "r"((A)[1]), "r"((A)[2]), "r"((A)[3]), "r"(b0), "r"(b1))

// ---- zero g_s (graph-replay safe) ----
__global__ __launch_bounds__(256) void zero_s() {
    ((float4*)g_s)[blockIdx.x * 256 + threadIdx.x] = make_float4(0.f, 0.f, 0.f, 0.f);
}

// ---- transpose + hi/lo split of x: [b][e][t] f32 -> [b][t][e] bf16 x2 ----
__global__ __launch_bounds__(256) void tsplit_x(const float* __restrict__ x) {
    __shared__ float tile[32][33];
    const int b = blockIdx.z, t0 = blockIdx.x * 32, e0 = blockIdx.y * 32;
    const int tx = threadIdx.x & 31, ty = threadIdx.x >> 5;
#pragma unroll
    for (int p = 0; p < 4; p++)
        tile[ty + 8 * p][tx] = x[((size_t)b * E_ + e0 + ty + 8 * p) * L_ + t0 + tx];
    __syncthreads();
#pragma unroll
    for (int p = 0; p < 4; p++) {
        int t = t0 + ty + 8 * p;
        float v = tile[tx][ty + 8 * p];
        __nv_bfloat16 h = __float2bfloat16(v);
        __nv_bfloat16 l = __float2bfloat16(v - __bfloat162float(h));
        size_t o = ((size_t)b * L_ + t) * E_ + e0 + tx;
        g_xth[o] = h;
        g_xtl[o] = l;
    }
}

// ---- weight re-layout + split: w[eo][ein][tap] -> [eo][tap][ein] bf16 x2 ----
__global__ __launch_bounds__(256) void split_w(const float* __restrict__ w) {
    int i = blockIdx.x * 256 + threadIdx.x;
    int eo = i / KT_;
    int r = i - eo * KT_;
    int tap = r >> 9, ei = r & 511;
    float v = w[(size_t)eo * KT_ + ei * KS_ + tap];
    __nv_bfloat16 h = __float2bfloat16(v);
    g_wh[i] = h;
    g_wl[i] = __float2bfloat16(v - __bfloat162float(h));
}

// ---- conv via mma.sync bf16: C[eo 128][t 128], 16 warps (32x32 tiles), fused score ----
__global__ __launch_bounds__(512, 1) void conv_mma(
    const float* __restrict__ bias, const float* __restrict__ swg)
{
    extern __shared__ __align__(16) char sm[];
    __shared__ float s_part[128];
    const uint32_t sb = smem_u32(sm);
    const int tid = threadIdx.x, lane = tid & 31, wid = tid >> 5;
    const int wm = wid & 3;        // eo 32-row block (0..3)
    const int wn = wid >> 2;       // t 32-col block (0..3)
    const int b = blockIdx.z, t0 = blockIdx.x * 128, eo0 = blockIdx.y * 128;

    float acc[2][4][4];
#pragma unroll
    for (int i = 0; i < 2; i++)
#pragma unroll
        for (int j = 0; j < 4; j++)
#pragma unroll
            for (int q = 0; q < 4; q++) acc[i][j][q] = 0.f;

    if (tid < 128) s_part[tid] = 0.f;

    const int lrow = tid >> 2, lq = tid & 3;   // 512 threads: 1x16B per tile each

    auto issue = [&](int c, int stage) {
        const int tap = c % KS_, ec = c / KS_;
        const uint32_t st = sb + stage * STAGE_B;
        const size_t woff = (size_t)eo0 * KT_ + tap * 512 + ec * BKc + lq * 8
                            + (size_t)lrow * KT_;
        CP16(st + 0 * TILE_B + lrow * ROWB + lq * 16, g_wh + woff);
        CP16(st + 1 * TILE_B + lrow * ROWB + lq * 16, g_wl + woff);
        int t = t0 + tap + lrow;
        if (t > L_ - 1) t = L_ - 1;   // clamp: only affects t>=LC_ outputs (zeroed below)
        const size_t xoff = ((size_t)b * L_ + t) * E_ + ec * BKc + lq * 8;
        CP16(st + 2 * TILE_B + lrow * ROWB + lq * 16, g_xth + xoff);
        CP16(st + 3 * TILE_B + lrow * ROWB + lq * 16, g_xtl + xoff);
    };

    issue(0, 0); CP_COMMIT();
    issue(1, 1); CP_COMMIT();

    const int lr = lane & 7, g = lane >> 3;

    for (int c = 0; c < NCH; c++) {
        CP_WAIT1();
        __syncthreads();

        const uint32_t st = sb + (c % 3) * STAGE_B;
#pragma unroll
        for (int kk = 0; kk < 2; kk++) {
            uint32_t ah[2][4], al[2][4], bh[4][2], bl[4][2];
#pragma unroll
            for (int i = 0; i < 2; i++) {
                uint32_t ra = st + (uint32_t)(wm * 32 + i * 16 + lr + (g & 1) * 8) * ROWB
                              + kk * 32 + (g >> 1) * 16;
                LDSM4(ah[i], ra);
                LDSM4(al[i], ra + TILE_B);
            }
#pragma unroll
            for (int j = 0; j < 2; j++) {
                uint32_t rb = st + 2 * TILE_B
                              + (uint32_t)(wn * 32 + j * 16 + lr + (g >> 1) * 8) * ROWB
                              + kk * 32 + (g & 1) * 16;
                uint32_t r4[4];
                LDSM4(r4, rb);
                bh[2 * j][0] = r4[0]; bh[2 * j][1] = r4[1];
                bh[2 * j + 1][0] = r4[2]; bh[2 * j + 1][1] = r4[3];
                LDSM4(r4, rb + TILE_B);
                bl[2 * j][0] = r4[0]; bl[2 * j][1] = r4[1];
                bl[2 * j + 1][0] = r4[2]; bl[2 * j + 1][1] = r4[3];
            }
#pragma unroll
            for (int i = 0; i < 2; i++)
#pragma unroll
                for (int j = 0; j < 4; j++) {
                    MMA(acc[i][j], ah[i], bh[j][0], bh[j][1]);
                    MMA(acc[i][j], ah[i], bl[j][0], bl[j][1]);
                    MMA(acc[i][j], al[i], bh[j][0], bh[j][1]);
                }
        }
        __syncthreads();
        if (c + 2 < NCH) issue(c + 2, (c + 2) % 3);
        CP_COMMIT();
    }

    // store y (+bias, zero t>=LC_) and accumulate partial scores into s_part
    const int l4 = lane >> 2, l2 = (lane & 3) * 2;
#pragma unroll
    for (int i = 0; i < 2; i++) {
        int eoA = eo0 + wm * 32 + i * 16 + l4;
        float bv0 = bias[eoA], bv1 = bias[eoA + 8];
        float sw0 = swg[eoA], sw1 = swg[eoA + 8];
        float* p0 = g_y + ((size_t)b * E_ + eoA) * L_;
        float* p1 = p0 + (size_t)8 * L_;
#pragma unroll
        for (int j = 0; j < 4; j++) {
            int tc = t0 + wn * 32 + j * 8 + l2;
            float y00 = (tc     < LC_) ? acc[i][j][0] + bv0 : 0.f;
            float y01 = (tc + 1 < LC_) ? acc[i][j][1] + bv0 : 0.f;
            float y10 = (tc     < LC_) ? acc[i][j][2] + bv1 : 0.f;
            float y11 = (tc + 1 < LC_) ? acc[i][j][3] + bv1 : 0.f;
            *reinterpret_cast<float2*>(p0 + tc) = make_float2(y00, y01);
            *reinterpret_cast<float2*>(p1 + tc) = make_float2(y10, y11);
            int o = wn * 32 + j * 8 + l2;
            atomicAdd(&s_part[o],     y00 * sw0 + y10 * sw1);
            atomicAdd(&s_part[o + 1], y01 * sw0 + y11 * sw1);
        }
    }
    __syncthreads();
    if (tid < 128) atomicAdd(&g_s[(size_t)b * L_ + t0 + tid], s_part[tid]);
}

// ---- softmax mix + downsample ----
#define OT 32
__global__ __launch_bounds__(256) void epilogue_kernel(float* __restrict__ out) {
    __shared__ float att[2 * OT][3];
    const int b = blockIdx.y, o0 = blockIdx.x * OT, tid = threadIdx.x;
    const float* sp = g_s + (size_t)b * L_;

    if (tid < 2 * OT) {
        int l = 2 * o0 + tid;
        float c1 = sp[l];
        int n2 = l >> 1;
        float c2 = 0.5f * (sp[2 * n2] + sp[2 * n2 + 1]);
        int n3 = l / 3;
        float c3 = (n3 < NB3_) ? (sp[3 * n3] + sp[3 * n3 + 1] + sp[3 * n3 + 2]) * (1.f / 3.f) : 0.f;
        float m = fmaxf(c1, fmaxf(c2, c3));
        float a1 = __expf(c1 - m), a2 = __expf(c2 - m), a3 = __expf(c3 - m);
        float inv = 1.f / (a1 + a2 + a3);
        att[tid][0] = a1 * inv; att[tid][1] = a2 * inv; att[tid][2] = a3 * inv;
    }
    __syncthreads();

    const float* yb = g_y + (size_t)b * E_ * L_;
    const int ol = tid & (OT - 1), o = o0 + ol;
    const int l0 = 2 * o, l1 = l0 + 1;
    const int n3a = l0 / 3, n3b = l1 / 3;
    const bool ok3a = (n3a < NB3_), ok3b = (n3b < NB3_);
    const float w10 = att[2 * ol][0], w20 = att[2 * ol][1], w30 = att[2 * ol][2];
    const float w11 = att[2 * ol + 1][0], w21 = att[2 * ol + 1][1], w31 = att[2 * ol + 1][2];

    for (int e = tid / OT; e < E_; e += 256 / OT) {
        const float* yr = yb + (size_t)e * L_;
        float ya = yr[l0], yv = yr[l1];
        float v2 = 0.5f * (ya + yv);
        float v3a = ok3a ? (yr[3 * n3a] + yr[3 * n3a + 1] + yr[3 * n3a + 2]) * (1.f / 3.f) : 0.f;
        float v3b = (n3b == n3a) ? v3a
                  : (ok3b ? (yr[3 * n3b] + yr[3 * n3b + 1] + yr[3 * n3b + 2]) * (1.f / 3.f) : 0.f);
        out[((size_t)b * E_ + e) * (L_ / 2) + o] =
            0.5f * ((ya * w10 + v2 * w20 + v3a * w30) + (yv * w11 + v2 * w21 + v3b * w31));
    }
}

extern "C" void kernel_launch(void* const* d_in, const int* in_sizes, int n_in,
                              void* d_out, int out_size) {
    const float* x = (const float*)d_in[0];
    const float* conv_w = (const float*)d_in[1];
    const float* conv_b = (const float*)d_in[2];
    const float* score_w = (const float*)d_in[3];
    float* out = (float*)d_out;

    zero_s<<<(B_ * L_) / 1024, 256>>>();

    dim3 gt(L_ / 32, E_ / 32, B_);
    tsplit_x<<<gt, 256>>>(x);
    split_w<<<(E_ * KT_) / 256, 256>>>(conv_w);

    static int smem_set = 0;
    if (!smem_set) {
        cudaFuncSetAttribute(conv_mma, cudaFuncAttributeMaxDynamicSharedMemorySize, CSMEM);
        smem_set = 1;
    }
    dim3 gc(L_ / 128, E_ / 128, B_);   // 64 x 4 x 8 = 2048 CTAs
    conv_mma<<<gc, 512, CSMEM>>>(conv_b, score_w);

    dim3 ge((L_ / 2) / OT, B_);
    epilogue_kernel<<<ge, 256>>>(out);
}

// round 8
// speedup vs baseline: 1.4084x; 1.4084x over previous
#include <cuda_runtime.h>
#include <cstdint>
#include <cuda_bf16.h>

#define B_ 8
#define E_ 512
#define L_ 8192
#define KS_ 5
#define LC_ (L_ - KS_ + 1)   // 8188
#define NB3_ 2730
#define KT_ (E_ * KS_)       // 2560

// conv tiling: CTA 128eo x 256t, 16 warps of 64x32; K chunks of 32 (5 taps x 16 e-chunks)
#define NCH 80
#define ROWB 80                       // padded smem row stride (64B payload)
#define A_TILE (128 * ROWB)           // 10240 (one of hi/lo)
#define A_STAGE (2 * A_TILE)          // 20480
#define B_ROWS 260
#define B_TILE (B_ROWS * ROWB)        // 20800
#define B_BUF (2 * B_TILE)            // 41600
#define OFF_B (3 * A_STAGE)           // 61440
#define CSMEM (OFF_B + 2 * B_BUF)     // 144640

__device__ float g_y[(size_t)B_ * E_ * L_];
__device__ float g_s[(size_t)B_ * L_];
__device__ __align__(16) __nv_bfloat16 g_xth[(size_t)B_ * L_ * E_]; // [b][t][e] hi
__device__ __align__(16) __nv_bfloat16 g_xtl[(size_t)B_ * L_ * E_]; // [b][t][e] lo
__device__ __align__(16) __nv_bfloat16 g_wh[(size_t)E_ * KT_];      // [eo][tap][ein]
__device__ __align__(16) __nv_bfloat16 g_wl[(size_t)E_ * KT_];

__device__ __forceinline__ uint32_t smem_u32(const void* p) {
    uint32_t a;
    asm("{ .reg .u64 t; cvta.to.shared.u64 t, %1; cvt.u32.u64 %0, t; }" : "=r"(a) : "l"(p));
    return a;
}
#define CP16(dst, src) \
    asm volatile("cp.async.cg.shared.global [%0], [%1], 16;" :: "r"(dst), "l"(src) : "memory")
#define CP_COMMIT() asm volatile("cp.async.commit_group;" ::: "memory")
#define CP_WAIT1() asm volatile("cp.async.wait_group 1;" ::: "memory")

#define LDSM4(r, a) \
    asm volatile("ldmatrix.sync.aligned.m8n8.x4.shared.b16 {%0,%1,%2,%3}, [%4];" \
        : "=r"((r)[0]), "=r"((r)[1]), "=r"((r)[2]), "=r"((r)[3]) : "r"(a))

#define MMA(c, A, b0, b1) \
    asm volatile("mma.sync.aligned.m16n8k16.row.col.f32.bf16.bf16.f32 " \
        "{%0,%1,%2,%3},{%4,%5,%6,%7},{%8,%9},{%0,%1,%2,%3};" \
        : "+f"((c)[0]), "+f"((c)[1]), "+f"((c)[2]), "+f"((c)[3]) \
        : "r"((A)[0]), "r"((A)[1]), "r"((A)[2]), "r"((A)[3]), "r"(b0), "r"(b1))

// ---- transpose + hi/lo split of x: [b][e][t] f32 -> [b][t][e] bf16 x2 ----
__global__ __launch_bounds__(256) void tsplit_x(const float* __restrict__ x) {
    __shared__ float tile[32][33];
    const int b = blockIdx.z, t0 = blockIdx.x * 32, e0 = blockIdx.y * 32;
    const int tx = threadIdx.x & 31, ty = threadIdx.x >> 5;
#pragma unroll
    for (int p = 0; p < 4; p++)
        tile[ty + 8 * p][tx] = x[((size_t)b * E_ + e0 + ty + 8 * p) * L_ + t0 + tx];
    __syncthreads();
#pragma unroll
    for (int p = 0; p < 4; p++) {
        int t = t0 + ty + 8 * p;
        float v = tile[tx][ty + 8 * p];
        __nv_bfloat16 h = __float2bfloat16(v);
        __nv_bfloat16 l = __float2bfloat16(v - __bfloat162float(h));
        size_t o = ((size_t)b * L_ + t) * E_ + e0 + tx;
        g_xth[o] = h;
        g_xtl[o] = l;
    }
}

// ---- weight re-layout + split: w[eo][ein][tap] -> [eo][tap][ein] bf16 x2 ----
__global__ __launch_bounds__(256) void split_w(const float* __restrict__ w) {
    int i = blockIdx.x * 256 + threadIdx.x;
    int eo = i / KT_;
    int r = i - eo * KT_;
    int tap = r >> 9, ei = r & 511;
    float v = w[(size_t)eo * KT_ + ei * KS_ + tap];
    __nv_bfloat16 h = __float2bfloat16(v);
    g_wh[i] = h;
    g_wl[i] = __float2bfloat16(v - __bfloat162float(h));
}

// ---- conv: C[eo 128][t 256], 16 warps (64x32), B tile shared across taps ----
__global__ __launch_bounds__(512, 1) void conv_mma(const float* __restrict__ bias) {
    extern __shared__ __align__(16) char sm[];
    const uint32_t sb = smem_u32(sm);
    const int tid = threadIdx.x, lane = tid & 31, wid = tid >> 5;
    const int wm = wid & 1;        // eo 64-half
    const int wn = wid >> 1;       // t 32-block (0..7)
    const int b = blockIdx.z, t0 = blockIdx.x * 256, eo0 = blockIdx.y * 128;

    float acc[4][4][4];
#pragma unroll
    for (int i = 0; i < 4; i++)
#pragma unroll
        for (int j = 0; j < 4; j++)
#pragma unroll
            for (int q = 0; q < 4; q++) acc[i][j][q] = 0.f;

    const int lrow = tid >> 2, lq = tid & 3;   // 128 loader rows x 4 16B-chunks

    auto issue = [&](int c) {
        const int tap = c % KS_, ec = c / KS_;
        const uint32_t stA = sb + (c % 3) * A_STAGE;
        const size_t woff = (size_t)(eo0 + lrow) * KT_ + tap * 512 + ec * 32 + lq * 8;
        CP16(stA + lrow * ROWB + lq * 16, g_wh + woff);
        CP16(stA + A_TILE + lrow * ROWB + lq * 16, g_wl + woff);
        if (tap == 0) {
            const uint32_t stB = sb + OFF_B + (ec & 1) * B_BUF;
#pragma unroll
            for (int h = 0; h < 2; h++) {
                int r = lrow + h * 128;
                int t = t0 + r; if (t > L_ - 1) t = L_ - 1;
                const size_t xoff = ((size_t)b * L_ + t) * E_ + ec * 32 + lq * 8;
                CP16(stB + r * ROWB + lq * 16, g_xth + xoff);
                CP16(stB + B_TILE + r * ROWB + lq * 16, g_xtl + xoff);
            }
            if (lrow < 4) {
                int r = 256 + lrow;
                int t = t0 + r; if (t > L_ - 1) t = L_ - 1;
                const size_t xoff = ((size_t)b * L_ + t) * E_ + ec * 32 + lq * 8;
                CP16(stB + r * ROWB + lq * 16, g_xth + xoff);
                CP16(stB + B_TILE + r * ROWB + lq * 16, g_xtl + xoff);
            }
        }
    };

    issue(0); CP_COMMIT();
    issue(1); CP_COMMIT();

    const int lr = lane & 7, g = lane >> 3;

    for (int c = 0; c < NCH; c++) {
        CP_WAIT1();
        __syncthreads();

        const int tap = c % KS_;
        const uint32_t stA = sb + (c % 3) * A_STAGE;
        const uint32_t stB = sb + OFF_B + ((c / KS_) & 1) * B_BUF;
#pragma unroll
        for (int kk = 0; kk < 2; kk++) {
            uint32_t ah[4][4], al[4][4], bh[4][2], bl[4][2];
#pragma unroll
            for (int i = 0; i < 4; i++) {
                uint32_t ra = stA + (uint32_t)(wm * 64 + i * 16 + lr + (g & 1) * 8) * ROWB
                              + kk * 32 + (g >> 1) * 16;
                LDSM4(ah[i], ra);
                LDSM4(al[i], ra + A_TILE);
            }
#pragma unroll
            for (int j = 0; j < 2; j++) {
                uint32_t rb = stB
                    + (uint32_t)(tap + wn * 32 + j * 16 + lr + (g >> 1) * 8) * ROWB
                    + kk * 32 + (g & 1) * 16;
                uint32_t r4[4];
                LDSM4(r4, rb);
                bh[2 * j][0] = r4[0]; bh[2 * j][1] = r4[1];
                bh[2 * j + 1][0] = r4[2]; bh[2 * j + 1][1] = r4[3];
                LDSM4(r4, rb + B_TILE);
                bl[2 * j][0] = r4[0]; bl[2 * j][1] = r4[1];
                bl[2 * j + 1][0] = r4[2]; bl[2 * j + 1][1] = r4[3];
            }
#pragma unroll
            for (int i = 0; i < 4; i++)
#pragma unroll
                for (int j = 0; j < 4; j++) {
                    MMA(acc[i][j], ah[i], bh[j][0], bh[j][1]);
                    MMA(acc[i][j], ah[i], bl[j][0], bl[j][1]);
                    MMA(acc[i][j], al[i], bh[j][0], bh[j][1]);
                }
        }
        __syncthreads();
        if (c + 2 < NCH) issue(c + 2);
        CP_COMMIT();
    }

    // store: acc -> g_y + bias, zero for t >= LC_
    const int l4 = lane >> 2, l2 = (lane & 3) * 2;
#pragma unroll
    for (int i = 0; i < 4; i++) {
        int eoA = eo0 + wm * 64 + i * 16 + l4;
        float bv0 = bias[eoA], bv1 = bias[eoA + 8];
        float* p0 = g_y + ((size_t)b * E_ + eoA) * L_;
        float* p1 = p0 + (size_t)8 * L_;
#pragma unroll
        for (int j = 0; j < 4; j++) {
            int tc = t0 + wn * 32 + j * 8 + l2;
            float2 v0, v1;
            v0.x = (tc     < LC_) ? acc[i][j][0] + bv0 : 0.f;
            v0.y = (tc + 1 < LC_) ? acc[i][j][1] + bv0 : 0.f;
            v1.x = (tc     < LC_) ? acc[i][j][2] + bv1 : 0.f;
            v1.y = (tc + 1 < LC_) ? acc[i][j][3] + bv1 : 0.f;
            *reinterpret_cast<float2*>(p0 + tc) = v0;
            *reinterpret_cast<float2*>(p1 + tc) = v1;
        }
    }
}

// ---- scores s[b,t] = <y[b,:,t], score_w> ----
__global__ __launch_bounds__(256) void score_kernel(const float* __restrict__ sw) {
    __shared__ float swv[E_];
    const int b = blockIdx.y;
    const int t = blockIdx.x * 256 + threadIdx.x;
    for (int i = threadIdx.x; i < E_; i += 256) swv[i] = sw[i];
    __syncthreads();
    const float* yb = g_y + (size_t)b * E_ * L_;
    float acc = 0.f;
#pragma unroll 8
    for (int e = 0; e < E_; e++) acc += yb[(size_t)e * L_ + t] * swv[e];
    g_s[(size_t)b * L_ + t] = acc;
}

// ---- softmax mix + downsample ----
#define OT 32
__global__ __launch_bounds__(256) void epilogue_kernel(float* __restrict__ out) {
    __shared__ float att[2 * OT][3];
    const int b = blockIdx.y, o0 = blockIdx.x * OT, tid = threadIdx.x;
    const float* sp = g_s + (size_t)b * L_;

    if (tid < 2 * OT) {
        int l = 2 * o0 + tid;
        float c1 = sp[l];
        int n2 = l >> 1;
        float c2 = 0.5f * (sp[2 * n2] + sp[2 * n2 + 1]);
        int n3 = l / 3;
        float c3 = (n3 < NB3_) ? (sp[3 * n3] + sp[3 * n3 + 1] + sp[3 * n3 + 2]) * (1.f / 3.f) : 0.f;
        float m = fmaxf(c1, fmaxf(c2, c3));
        float a1 = __expf(c1 - m), a2 = __expf(c2 - m), a3 = __expf(c3 - m);
        float inv = 1.f / (a1 + a2 + a3);
        att[tid][0] = a1 * inv; att[tid][1] = a2 * inv; att[tid][2] = a3 * inv;
    }
    __syncthreads();

    const float* yb = g_y + (size_t)b * E_ * L_;
    const int ol = tid & (OT - 1), o = o0 + ol;
    const int l0 = 2 * o, l1 = l0 + 1;
    const int n3a = l0 / 3, n3b = l1 / 3;
    const bool ok3a = (n3a < NB3_), ok3b = (n3b < NB3_);
    const float w10 = att[2 * ol][0], w20 = att[2 * ol][1], w30 = att[2 * ol][2];
    const float w11 = att[2 * ol + 1][0], w21 = att[2 * ol + 1][1], w31 = att[2 * ol + 1][2];

    for (int e = tid / OT; e < E_; e += 256 / OT) {
        const float* yr = yb + (size_t)e * L_;
        float ya = yr[l0], yv = yr[l1];
        float v2 = 0.5f * (ya + yv);
        float v3a = ok3a ? (yr[3 * n3a] + yr[3 * n3a + 1] + yr[3 * n3a + 2]) * (1.f / 3.f) : 0.f;
        float v3b = (n3b == n3a) ? v3a
                  : (ok3b ? (yr[3 * n3b] + yr[3 * n3b + 1] + yr[3 * n3b + 2]) * (1.f / 3.f) : 0.f);
        out[((size_t)b * E_ + e) * (L_ / 2) + o] =
            0.5f * ((ya * w10 + v2 * w20 + v3a * w30) + (yv * w11 + v2 * w21 + v3b * w31));
    }
}

extern "C" void kernel_launch(void* const* d_in, const int* in_sizes, int n_in,
                              void* d_out, int out_size) {
    const float* x = (const float*)d_in[0];
    const float* conv_w = (const float*)d_in[1];
    const float* conv_b = (const float*)d_in[2];
    const float* score_w = (const float*)d_in[3];
    float* out = (float*)d_out;

    dim3 gt(L_ / 32, E_ / 32, B_);
    tsplit_x<<<gt, 256>>>(x);
    split_w<<<(E_ * KT_) / 256, 256>>>(conv_w);

    static int smem_set = 0;
    if (!smem_set) {
        cudaFuncSetAttribute(conv_mma, cudaFuncAttributeMaxDynamicSharedMemorySize, CSMEM);
        smem_set = 1;
    }
    dim3 gc(L_ / 256, E_ / 128, B_);   // 32 x 4 x 8 = 1024 CTAs
    conv_mma<<<gc, 512, CSMEM>>>(conv_b);

    dim3 gs(L_ / 256, B_);
    score_kernel<<<gs, 256>>>(score_w);

    dim3 ge((L_ / 2) / OT, B_);
    epilogue_kernel<<<ge, 256>>>(out);
}

// round 9
// speedup vs baseline: 1.4319x; 1.0167x over previous
#include <cuda_runtime.h>
#include <cstdint>
#include <cuda_bf16.h>

#define B_ 8
#define E_ 512
#define L_ 8192
#define KS_ 5
#define LC_ (L_ - KS_ + 1)   // 8188
#define NB3_ 2730
#define KT_ (E_ * KS_)       // 2560

// conv tiling: CTA 128eo x 256t, 16 warps of 64x32; K chunks of 32 (5 taps x 16 e-chunks)
#define NCH 80
#define ROWB 80                       // padded smem row stride (64B payload)
#define A_TILE (128 * ROWB)           // 10240 (one of hi/lo)
#define A_STAGE (2 * A_TILE)          // 20480
#define B_ROWS 260
#define B_TILE (B_ROWS * ROWB)        // 20800
#define B_BUF (2 * B_TILE)            // 41600
#define OFF_B (3 * A_STAGE)           // 61440
#define CSMEM (OFF_B + 2 * B_BUF)     // 144640

__device__ float g_y[(size_t)B_ * E_ * L_];
__device__ float g_s[(size_t)B_ * L_];
__device__ __align__(16) __nv_bfloat16 g_xth[(size_t)B_ * L_ * E_]; // [b][t][e] hi
__device__ __align__(16) __nv_bfloat16 g_xtl[(size_t)B_ * L_ * E_]; // [b][t][e] lo
__device__ __align__(16) __nv_bfloat16 g_wh[(size_t)E_ * KT_];      // [eo][tap][ein]
__device__ __align__(16) __nv_bfloat16 g_wl[(size_t)E_ * KT_];

__device__ __forceinline__ uint32_t smem_u32(const void* p) {
    uint32_t a;
    asm("{ .reg .u64 t; cvta.to.shared.u64 t, %1; cvt.u32.u64 %0, t; }" : "=r"(a) : "l"(p));
    return a;
}
#define CP16(dst, src) \
    asm volatile("cp.async.cg.shared.global [%0], [%1], 16;" :: "r"(dst), "l"(src) : "memory")
#define CP_COMMIT() asm volatile("cp.async.commit_group;" ::: "memory")
#define CP_WAIT2() asm volatile("cp.async.wait_group 2;" ::: "memory")

#define LDSM4(r, a) \
    asm volatile("ldmatrix.sync.aligned.m8n8.x4.shared.b16 {%0,%1,%2,%3}, [%4];" \
        : "=r"((r)[0]), "=r"((r)[1]), "=r"((r)[2]), "=r"((r)[3]) : "r"(a))

#define MMA(c, A, b0, b1) \
    asm volatile("mma.sync.aligned.m16n8k16.row.col.f32.bf16.bf16.f32 " \
        "{%0,%1,%2,%3},{%4,%5,%6,%7},{%8,%9},{%0,%1,%2,%3};" \
        : "+f"((c)[0]), "+f"((c)[1]), "+f"((c)[2]), "+f"((c)[3]) \
        : "r"((A)[0]), "r"((A)[1]), "r"((A)[2]), "r"((A)[3]), "r"(b0), "r"(b1))

// ---- transpose + hi/lo split of x: [b][e][t] f32 -> [b][t][e] bf16 x2 ----
__global__ __launch_bounds__(256) void tsplit_x(const float* __restrict__ x) {
    __shared__ float tile[32][33];
    const int b = blockIdx.z, t0 = blockIdx.x * 32, e0 = blockIdx.y * 32;
    const int tx = threadIdx.x & 31, ty = threadIdx.x >> 5;
#pragma unroll
    for (int p = 0; p < 4; p++)
        tile[ty + 8 * p][tx] = x[((size_t)b * E_ + e0 + ty + 8 * p) * L_ + t0 + tx];
    __syncthreads();
#pragma unroll
    for (int p = 0; p < 4; p++) {
        int t = t0 + ty + 8 * p;
        float v = tile[tx][ty + 8 * p];
        __nv_bfloat16 h = __float2bfloat16(v);
        __nv_bfloat16 l = __float2bfloat16(v - __bfloat162float(h));
        size_t o = ((size_t)b * L_ + t) * E_ + e0 + tx;
        g_xth[o] = h;
        g_xtl[o] = l;
    }
}

// ---- weight re-layout + split: w[eo][ein][tap] -> [eo][tap][ein] bf16 x2 ----
__global__ __launch_bounds__(256) void split_w(const float* __restrict__ w) {
    int i = blockIdx.x * 256 + threadIdx.x;
    int eo = i / KT_;
    int r = i - eo * KT_;
    int tap = r >> 9, ei = r & 511;
    float v = w[(size_t)eo * KT_ + ei * KS_ + tap];
    __nv_bfloat16 h = __float2bfloat16(v);
    g_wh[i] = h;
    g_wl[i] = __float2bfloat16(v - __bfloat162float(h));
}

// ---- conv: C[eo 128][t 256], 16 warps (64x32), B tile shared across taps ----
__global__ __launch_bounds__(512, 1) void conv_mma(const float* __restrict__ bias) {
    extern __shared__ __align__(16) char sm[];
    const uint32_t sb = smem_u32(sm);
    const int tid = threadIdx.x, lane = tid & 31, wid = tid >> 5;
    const int wm = wid & 1;        // eo 64-half
    const int wn = wid >> 1;       // t 32-block (0..7)
    const int b = blockIdx.z, t0 = blockIdx.x * 256, eo0 = blockIdx.y * 128;

    float acc[4][4][4];
#pragma unroll
    for (int i = 0; i < 4; i++)
#pragma unroll
        for (int j = 0; j < 4; j++)
#pragma unroll
            for (int q = 0; q < 4; q++) acc[i][j][q] = 0.f;

    const int lrow = tid >> 2, lq = tid & 3;   // 128 loader rows x 4 16B-chunks

    auto issue = [&](int c) {
        const int tap = c % KS_, ec = c / KS_;
        const uint32_t stA = sb + (c % 3) * A_STAGE;
        const size_t woff = (size_t)(eo0 + lrow) * KT_ + tap * 512 + ec * 32 + lq * 8;
        CP16(stA + lrow * ROWB + lq * 16, g_wh + woff);
        CP16(stA + A_TILE + lrow * ROWB + lq * 16, g_wl + woff);
        if (tap == 0) {
            const uint32_t stB = sb + OFF_B + (ec & 1) * B_BUF;
#pragma unroll
            for (int h = 0; h < 2; h++) {
                int r = lrow + h * 128;
                int t = t0 + r; if (t > L_ - 1) t = L_ - 1;
                const size_t xoff = ((size_t)b * L_ + t) * E_ + ec * 32 + lq * 8;
                CP16(stB + r * ROWB + lq * 16, g_xth + xoff);
                CP16(stB + B_TILE + r * ROWB + lq * 16, g_xtl + xoff);
            }
            if (lrow < 4) {
                int r = 256 + lrow;
                int t = t0 + r; if (t > L_ - 1) t = L_ - 1;
                const size_t xoff = ((size_t)b * L_ + t) * E_ + ec * 32 + lq * 8;
                CP16(stB + r * ROWB + lq * 16, g_xth + xoff);
                CP16(stB + B_TILE + r * ROWB + lq * 16, g_xtl + xoff);
            }
        }
    };

    issue(0); CP_COMMIT();
    issue(1); CP_COMMIT();

    const int lr = lane & 7, g = lane >> 3;

    for (int c = 0; c < NCH; c++) {
        // issue chunk c+2 FIRST (its target stage was vacated after chunk c-1),
        // then wait for chunk c's group. Groups in flight <= 2 -> wait_group 2
        // guarantees groups 0..c complete.
        if (c + 2 < NCH) { issue(c + 2); }
        CP_COMMIT();
        CP_WAIT2();
        __syncthreads();   // all warps past chunk c-1; chunk c data visible to all

        const int tap = c % KS_;
        const uint32_t stA = sb + (c % 3) * A_STAGE;
        const uint32_t stB = sb + OFF_B + ((c / KS_) & 1) * B_BUF;
#pragma unroll
        for (int kk = 0; kk < 2; kk++) {
            uint32_t ah[4][4], al[4][4], bh[4][2], bl[4][2];
#pragma unroll
            for (int i = 0; i < 4; i++) {
                uint32_t ra = stA + (uint32_t)(wm * 64 + i * 16 + lr + (g & 1) * 8) * ROWB
                              + kk * 32 + (g >> 1) * 16;
                LDSM4(ah[i], ra);
                LDSM4(al[i], ra + A_TILE);
            }
#pragma unroll
            for (int j = 0; j < 2; j++) {
                uint32_t rb = stB
                    + (uint32_t)(tap + wn * 32 + j * 16 + lr + (g >> 1) * 8) * ROWB
                    + kk * 32 + (g & 1) * 16;
                uint32_t r4[4];
                LDSM4(r4, rb);
                bh[2 * j][0] = r4[0]; bh[2 * j][1] = r4[1];
                bh[2 * j + 1][0] = r4[2]; bh[2 * j + 1][1] = r4[3];
                LDSM4(r4, rb + B_TILE);
                bl[2 * j][0] = r4[0]; bl[2 * j][1] = r4[1];
                bl[2 * j + 1][0] = r4[2]; bl[2 * j + 1][1] = r4[3];
            }
#pragma unroll
            for (int i = 0; i < 4; i++)
#pragma unroll
                for (int j = 0; j < 4; j++) {
                    MMA(acc[i][j], ah[i], bh[j][0], bh[j][1]);
                    MMA(acc[i][j], ah[i], bl[j][0], bl[j][1]);
                    MMA(acc[i][j], al[i], bh[j][0], bh[j][1]);
                }
        }
        __syncthreads();   // all reads of chunk c done before next iter's issue overwrites
    }

    // store: acc -> g_y + bias, zero for t >= LC_
    const int l4 = lane >> 2, l2 = (lane & 3) * 2;
#pragma unroll
    for (int i = 0; i < 4; i++) {
        int eoA = eo0 + wm * 64 + i * 16 + l4;
        float bv0 = bias[eoA], bv1 = bias[eoA + 8];
        float* p0 = g_y + ((size_t)b * E_ + eoA) * L_;
        float* p1 = p0 + (size_t)8 * L_;
#pragma unroll
        for (int j = 0; j < 4; j++) {
            int tc = t0 + wn * 32 + j * 8 + l2;
            float2 v0, v1;
            v0.x = (tc     < LC_) ? acc[i][j][0] + bv0 : 0.f;
            v0.y = (tc + 1 < LC_) ? acc[i][j][1] + bv0 : 0.f;
            v1.x = (tc     < LC_) ? acc[i][j][2] + bv1 : 0.f;
            v1.y = (tc + 1 < LC_) ? acc[i][j][3] + bv1 : 0.f;
            *reinterpret_cast<float2*>(p0 + tc) = v0;
            *reinterpret_cast<float2*>(p1 + tc) = v1;
        }
    }
}

// ---- scores s[b,t] = <y[b,:,t], score_w>, 4-way e-split for occupancy ----
__global__ __launch_bounds__(256) void score_kernel(const float* __restrict__ sw) {
    __shared__ float swv[E_];
    __shared__ float red[4][64];
    const int tid = threadIdx.x;
    const int b = blockIdx.y;
    const int tl = tid & 63;
    const int eg = tid >> 6;                       // 0..3: e-range split
    const int t = blockIdx.x * 64 + tl;
    for (int i = tid; i < E_; i += 256) swv[i] = sw[i];
    __syncthreads();
    const float* yb = g_y + (size_t)b * E_ * L_ + (size_t)eg * 128 * L_ + t;
    float acc = 0.f;
#pragma unroll 16
    for (int e = 0; e < 128; e++) acc += yb[(size_t)e * L_] * swv[eg * 128 + e];
    red[eg][tl] = acc;
    __syncthreads();
    if (eg == 0)
        g_s[(size_t)b * L_ + t] = red[0][tl] + red[1][tl] + red[2][tl] + red[3][tl];
}

// ---- softmax mix + downsample ----
#define OT 32
__global__ __launch_bounds__(256) void epilogue_kernel(float* __restrict__ out) {
    __shared__ float att[2 * OT][3];
    const int b = blockIdx.y, o0 = blockIdx.x * OT, tid = threadIdx.x;
    const float* sp = g_s + (size_t)b * L_;

    if (tid < 2 * OT) {
        int l = 2 * o0 + tid;
        float c1 = sp[l];
        int n2 = l >> 1;
        float c2 = 0.5f * (sp[2 * n2] + sp[2 * n2 + 1]);
        int n3 = l / 3;
        float c3 = (n3 < NB3_) ? (sp[3 * n3] + sp[3 * n3 + 1] + sp[3 * n3 + 2]) * (1.f / 3.f) : 0.f;
        float m = fmaxf(c1, fmaxf(c2, c3));
        float a1 = __expf(c1 - m), a2 = __expf(c2 - m), a3 = __expf(c3 - m);
        float inv = 1.f / (a1 + a2 + a3);
        att[tid][0] = a1 * inv; att[tid][1] = a2 * inv; att[tid][2] = a3 * inv;
    }
    __syncthreads();

    const float* yb = g_y + (size_t)b * E_ * L_;
    const int ol = tid & (OT - 1), o = o0 + ol;
    const int l0 = 2 * o, l1 = l0 + 1;
    const int n3a = l0 / 3, n3b = l1 / 3;
    const bool ok3a = (n3a < NB3_), ok3b = (n3b < NB3_);
    const float w10 = att[2 * ol][0], w20 = att[2 * ol][1], w30 = att[2 * ol][2];
    const float w11 = att[2 * ol + 1][0], w21 = att[2 * ol + 1][1], w31 = att[2 * ol + 1][2];

    for (int e = tid / OT; e < E_; e += 256 / OT) {
        const float* yr = yb + (size_t)e * L_;
        float ya = yr[l0], yv = yr[l1];
        float v2 = 0.5f * (ya + yv);
        float v3a = ok3a ? (yr[3 * n3a] + yr[3 * n3a + 1] + yr[3 * n3a + 2]) * (1.f / 3.f) : 0.f;
        float v3b = (n3b == n3a) ? v3a
                  : (ok3b ? (yr[3 * n3b] + yr[3 * n3b + 1] + yr[3 * n3b + 2]) * (1.f / 3.f) : 0.f);
        out[((size_t)b * E_ + e) * (L_ / 2) + o] =
            0.5f * ((ya * w10 + v2 * w20 + v3a * w30) + (yv * w11 + v2 * w21 + v3b * w31));
    }
}

extern "C" void kernel_launch(void* const* d_in, const int* in_sizes, int n_in,
                              void* d_out, int out_size) {
    const float* x = (const float*)d_in[0];
    const float* conv_w = (const float*)d_in[1];
    const float* conv_b = (const float*)d_in[2];
    const float* score_w = (const float*)d_in[3];
    float* out = (float*)d_out;

    dim3 gt(L_ / 32, E_ / 32, B_);
    tsplit_x<<<gt, 256>>>(x);
    split_w<<<(E_ * KT_) / 256, 256>>>(conv_w);

    static int smem_set = 0;
    if (!smem_set) {
        cudaFuncSetAttribute(conv_mma, cudaFuncAttributeMaxDynamicSharedMemorySize, CSMEM);
        smem_set = 1;
    }
    dim3 gc(L_ / 256, E_ / 128, B_);   // 32 x 4 x 8 = 1024 CTAs
    conv_mma<<<gc, 512, CSMEM>>>(conv_b);

    dim3 gs(L_ / 64, B_);              // 128 x 8 = 1024 blocks
    score_kernel<<<gs, 256>>>(score_w);

    dim3 ge((L_ / 2) / OT, B_);
    epilogue_kernel<<<ge, 256>>>(out);
}